// round 2
// baseline (speedup 1.0000x reference)
#include <cuda_runtime.h>
#include <cstdint>
#include <math.h>

// Problem dims
#define B   128
#define S   12
#define L   128
#define E   512
#define E2  1024
#define H   512
#define G3  1536     // 3*H
#define KIN 2304     // E2 + 2V + P

// ---------------- scratch (device globals, no allocation) ----------------
__device__ __align__(256) int   g_idx[B];
__device__ __align__(256) int   g_gc[B];
__device__ __align__(256) float g_inps[B * S * E2];       // 6.3 MB
__device__ __align__(256) float g_h0[B * H];
__device__ __align__(256) float g_xproj[B * S * G3];      // 9.4 MB
__device__ __align__(256) float g_gh[B * G3];
__device__ __align__(256) float g_outputs[B * S * H];     // 3.1 MB
__device__ __align__(256) float g_hpart[B * S * E];       // 3.1 MB
__device__ __align__(256) float g_epart[B * L * E];       // 33.5 MB
__device__ double g_acc[2];                               // stop_sum, group_sum

// ---------------- helpers ----------------
__device__ __forceinline__ float softplusf(float x) {
    return fmaxf(x, 0.f) + log1pf(expf(-fabsf(x)));
}
__device__ __forceinline__ float sigmoidf_(float x) {
    return 1.f / (1.f + expf(-x));
}
__device__ __forceinline__ float tanh_approx(float x) {
    float y;
    asm("tanh.approx.f32 %0, %1;" : "=f"(y) : "f"(x));
    return y;
}

// ---------------- 0: zero accumulators ----------------
__global__ void zero_acc_kernel() {
    if (threadIdx.x < 2) g_acc[threadIdx.x] = 0.0;
}

// ---------------- 1: stable descending argsort of group_count ----------------
__global__ void sort_kernel(const int* __restrict__ group_count) {
    __shared__ int s_gc[B];
    int i = threadIdx.x;
    int gci = group_count[i];
    s_gc[i] = gci;
    __syncthreads();
    int rank = 0;
    #pragma unroll 8
    for (int j = 0; j < B; j++) {
        int gj = s_gc[j];
        rank += (gj > gci) || (gj == gci && j < i);
    }
    g_idx[rank] = i;
    g_gc[rank]  = gci;
}

// ---------------- 2: inps = alpha @ enc_states  (per-batch block) ----------------
// alpha comes from SORTED segments (via g_idx); enc stays in ORIGINAL order,
// matching the reference, which permutes only segments/group_count.
__global__ void __launch_bounds__(256) inps_kernel(const float* __restrict__ enc,
                                                   const int* __restrict__ segments) {
    __shared__ float s_a[S][L];
    int b = blockIdx.x, tid = threadIdx.x;
    int src = g_idx[b];

    for (int i = tid; i < S * L; i += 256) {
        int s = i >> 7, l = i & 127;
        int v = (s == 0) ? 0 : segments[(src * S + (s - 1)) * L + l];
        s_a[s][l] = (float)v;
    }
    __syncthreads();
    if (tid < S) {
        float su = 0.f;
        for (int l = 0; l < L; l++) su += s_a[tid][l];
        float inv = 1.f / (su + 1.f);
        for (int l = 0; l < L; l++) s_a[tid][l] *= inv;
    }
    __syncthreads();

    float4 acc[S];
    #pragma unroll
    for (int s = 0; s < S; s++) acc[s] = make_float4(0.f, 0.f, 0.f, 0.f);

    const float* encb = enc + (size_t)b * L * E2;
    int e0 = tid * 4;
    for (int l = 0; l < L; l++) {
        float4 v = *(const float4*)(encb + l * E2 + e0);
        #pragma unroll
        for (int s = 0; s < S; s++) {
            float a = s_a[s][l];
            acc[s].x += a * v.x; acc[s].y += a * v.y;
            acc[s].z += a * v.z; acc[s].w += a * v.w;
        }
    }
    #pragma unroll
    for (int s = 0; s < S; s++)
        *(float4*)(g_inps + ((size_t)(b * S + s)) * E2 + e0) = acc[s];
}

// ---------------- generic GEMM:  C[m,n] = bias[n] + sum_k A[m,k]*W[n,k] ----------
// Big config: BM=BN=128, BK=8, 256 threads, 8x8 micro-tile.
__global__ void __launch_bounds__(256) gemm_nt_128(const float* __restrict__ A, int lda,
                                                   const float* __restrict__ W, int ldw,
                                                   const float* __restrict__ bias,
                                                   float* __restrict__ C, int ldc, int K) {
    __shared__ float As[8][128];
    __shared__ float Ws[8][128];
    const int bm = blockIdx.y * 128, bn = blockIdx.x * 128;
    const int tid = threadIdx.x;
    const int tx = tid & 15, ty = tid >> 4;
    const int lr = tid >> 1;            // 0..127
    const int lk = (tid & 1) * 4;       // 0 or 4

    const float* Ap = A + (size_t)(bm + lr) * lda + lk;
    const float* Wp = W + (size_t)(bn + lr) * ldw + lk;

    float acc[8][8];
    #pragma unroll
    for (int i = 0; i < 8; i++)
        #pragma unroll
        for (int j = 0; j < 8; j++) acc[i][j] = 0.f;

    for (int k0 = 0; k0 < K; k0 += 8) {
        float4 a4 = *(const float4*)(Ap + k0);
        float4 w4 = *(const float4*)(Wp + k0);
        As[lk + 0][lr] = a4.x; As[lk + 1][lr] = a4.y;
        As[lk + 2][lr] = a4.z; As[lk + 3][lr] = a4.w;
        Ws[lk + 0][lr] = w4.x; Ws[lk + 1][lr] = w4.y;
        Ws[lk + 2][lr] = w4.z; Ws[lk + 3][lr] = w4.w;
        __syncthreads();
        #pragma unroll
        for (int k = 0; k < 8; k++) {
            float ar[8], wr[8];
            *(float4*)(ar)     = *(const float4*)&As[k][ty * 8];
            *(float4*)(ar + 4) = *(const float4*)&As[k][ty * 8 + 4];
            *(float4*)(wr)     = *(const float4*)&Ws[k][tx * 8];
            *(float4*)(wr + 4) = *(const float4*)&Ws[k][tx * 8 + 4];
            #pragma unroll
            for (int i = 0; i < 8; i++)
                #pragma unroll
                for (int j = 0; j < 8; j++) acc[i][j] += ar[i] * wr[j];
        }
        __syncthreads();
    }

    float bv[8];
    #pragma unroll
    for (int j = 0; j < 8; j++) bv[j] = bias ? __ldg(&bias[bn + tx * 8 + j]) : 0.f;
    #pragma unroll
    for (int i = 0; i < 8; i++) {
        float4 r0 = make_float4(acc[i][0] + bv[0], acc[i][1] + bv[1],
                                acc[i][2] + bv[2], acc[i][3] + bv[3]);
        float4 r1 = make_float4(acc[i][4] + bv[4], acc[i][5] + bv[5],
                                acc[i][6] + bv[6], acc[i][7] + bv[7]);
        float* Cp = C + (size_t)(bm + ty * 8 + i) * ldc + bn + tx * 8;
        *(float4*)(Cp)     = r0;
        *(float4*)(Cp + 4) = r1;
    }
}

// Skinny config: BM=16, BN=64, BK=16, 128 threads, 2x4 micro-tile.
__global__ void __launch_bounds__(128) gemm_nt_small(const float* __restrict__ A, int lda,
                                                     const float* __restrict__ W, int ldw,
                                                     const float* __restrict__ bias,
                                                     float* __restrict__ C, int ldc, int K) {
    __shared__ float As[16][16];
    __shared__ float Ws[16][64];
    const int bm = blockIdx.y * 16, bn = blockIdx.x * 64;
    const int tid = threadIdx.x;
    const int tx = tid & 15, ty = tid >> 4;

    float acc[2][4];
    #pragma unroll
    for (int i = 0; i < 2; i++)
        #pragma unroll
        for (int j = 0; j < 4; j++) acc[i][j] = 0.f;

    for (int k0 = 0; k0 < K; k0 += 16) {
        // load A tile (16x16 = 256 floats, 2 per thread)
        #pragma unroll
        for (int it = 0; it < 2; it++) {
            int idx = tid + it * 128;
            int r = idx >> 4, kk = idx & 15;
            As[kk][r] = A[(size_t)(bm + r) * lda + k0 + kk];
        }
        // load W tile (64x16 = 1024 floats, 8 per thread as 2x float4)
        #pragma unroll
        for (int it = 0; it < 2; it++) {
            int r  = (tid >> 2) + it * 32;
            int kk = (tid & 3) * 4;
            float4 w4 = *(const float4*)(W + (size_t)(bn + r) * ldw + k0 + kk);
            Ws[kk + 0][r] = w4.x; Ws[kk + 1][r] = w4.y;
            Ws[kk + 2][r] = w4.z; Ws[kk + 3][r] = w4.w;
        }
        __syncthreads();
        #pragma unroll
        for (int k = 0; k < 16; k++) {
            float a0 = As[k][ty * 2], a1 = As[k][ty * 2 + 1];
            float4 wv = *(const float4*)&Ws[k][tx * 4];
            acc[0][0] += a0 * wv.x; acc[0][1] += a0 * wv.y;
            acc[0][2] += a0 * wv.z; acc[0][3] += a0 * wv.w;
            acc[1][0] += a1 * wv.x; acc[1][1] += a1 * wv.y;
            acc[1][2] += a1 * wv.z; acc[1][3] += a1 * wv.w;
        }
        __syncthreads();
    }

    float bv[4];
    #pragma unroll
    for (int j = 0; j < 4; j++) bv[j] = bias ? __ldg(&bias[bn + tx * 4 + j]) : 0.f;
    #pragma unroll
    for (int i = 0; i < 2; i++) {
        float4 r = make_float4(acc[i][0] + bv[0], acc[i][1] + bv[1],
                               acc[i][2] + bv[2], acc[i][3] + bv[3]);
        *(float4*)(C + (size_t)(bm + ty * 2 + i) * ldc + bn + tx * 4) = r;
    }
}

// ---------------- GRU gates (after gh GEMM for step s) ----------------
__global__ void __launch_bounds__(256) gate_kernel(int s) {
    int idx = blockIdx.x * blockDim.x + threadIdx.x;   // B*H = 65536
    int b = idx >> 9, j = idx & 511;
    const float* xp = g_xproj + (size_t)(b * S + s) * G3;
    const float* gh = g_gh + (size_t)b * G3;
    float ir = xp[j], iz = xp[H + j], inn = xp[2 * H + j];
    float hr = gh[j], hz = gh[H + j], hn  = gh[2 * H + j];
    float r = sigmoidf_(ir + hr);
    float z = sigmoidf_(iz + hz);
    float n = tanhf(inn + r * hn);
    float hp = s ? g_outputs[(size_t)(b * S + s - 1) * H + j] : g_h0[(size_t)b * H + j];
    g_outputs[(size_t)(b * S + s) * H + j] = (1.f - z) * n + z * hp;
}

// ---------------- stop loss ----------------
__global__ void __launch_bounds__(128) stop_loss_kernel(const float* __restrict__ W_stop,
                                                        const float* __restrict__ b_stop) {
    __shared__ float s_w[H];
    int b = blockIdx.x, tid = threadIdx.x;
    int gcb = g_gc[b];
    for (int i = tid; i < H; i += 128) s_w[i] = W_stop[i];
    __syncthreads();
    int w = tid >> 5, lane = tid & 31;
    float acc = 0.f;
    float bs = __ldg(b_stop);
    for (int s = w; s < gcb; s += 4) {
        const float* h = g_outputs + (size_t)(b * S + s) * H;
        float p = 0.f;
        for (int j = lane; j < H; j += 32) p += h[j] * s_w[j];
        #pragma unroll
        for (int off = 16; off; off >>= 1) p += __shfl_down_sync(0xffffffffu, p, off);
        if (lane == 0) {
            float logit = p + bs;
            float lab = (s == gcb - 1) ? 1.f : 0.f;
            acc += softplusf(logit) - logit * lab;
        }
    }
    if (lane == 0) atomicAdd(&g_acc[0], (double)acc);
}

// ---------------- group (plan) loss: fused tanh-score + BCE + reduce ----------------
__global__ void __launch_bounds__(256) group_loss_kernel(const int* __restrict__ segments,
                                                         const float* __restrict__ W_p2,
                                                         const float* __restrict__ b_p2) {
    __shared__ float s_h[S * E];    // 24 KB
    __shared__ float s_w2[E];
    __shared__ float s_ep[E];
    __shared__ float s_tg[S * L];   // 6 KB
    int b = blockIdx.x, tid = threadIdx.x;
    int src = g_idx[b], gcb = g_gc[b];

    for (int i = tid; i < E; i += 256) s_w2[i] = W_p2[i];
    for (int i = tid; i < S * E; i += 256) s_h[i] = g_hpart[(size_t)b * S * E + i];
    for (int i = tid; i < S * L; i += 256) s_tg[i] = (float)segments[(size_t)src * S * L + i];
    __syncthreads();

    int w = tid >> 5, lane = tid & 31;
    float bp2 = __ldg(b_p2);
    float accw = 0.f;

    for (int l = 0; l < L; l++) {
        const float* ep = g_epart + (size_t)(b * L + l) * E;
        s_ep[tid]       = ep[tid];
        s_ep[tid + 256] = ep[tid + 256];
        __syncthreads();
        for (int s = w; s < gcb; s += 8) {
            const float* hs = &s_h[s * E];
            float p = 0.f;
            #pragma unroll 4
            for (int e = lane; e < E; e += 32)
                p += tanh_approx(hs[e] + s_ep[e]) * s_w2[e];
            #pragma unroll
            for (int off = 16; off; off >>= 1) p += __shfl_down_sync(0xffffffffu, p, off);
            if (lane == 0) {
                float logit = p + bp2;
                float t = s_tg[s * L + l];
                accw += softplusf(logit) - logit * t;
            }
        }
        __syncthreads();
    }
    if (lane == 0) atomicAdd(&g_acc[1], (double)accw);
}

// ---------------- finalize ----------------
__global__ void finalize_kernel(float* out) {
    double ms = 0.0;
    for (int b = 0; b < B; b++) ms += (double)g_gc[b];
    out[0] = (float)(g_acc[0] / ms);
    out[1] = (float)(g_acc[1] / (ms * (double)L));
}

// ---------------- launch ----------------
extern "C" void kernel_launch(void* const* d_in, const int* in_sizes, int n_in,
                              void* d_out, int out_size) {
    (void)in_sizes; (void)n_in; (void)out_size;
    const float* enc        = (const float*)d_in[0];
    const int*   segments   = (const int*)d_in[1];
    const int*   group_cnt  = (const int*)d_in[2];
    const float* init_state = (const float*)d_in[3];
    const float* W_init     = (const float*)d_in[4];
    const float* b_init     = (const float*)d_in[5];
    const float* W_ih       = (const float*)d_in[6];
    const float* b_ih       = (const float*)d_in[7];
    const float* W_hh       = (const float*)d_in[8];
    const float* b_hh       = (const float*)d_in[9];
    const float* W_p1       = (const float*)d_in[10];
    const float* b_p1       = (const float*)d_in[11];
    const float* W_p2       = (const float*)d_in[12];
    const float* b_p2       = (const float*)d_in[13];
    const float* W_stop     = (const float*)d_in[14];
    const float* b_stop     = (const float*)d_in[15];
    float* out = (float*)d_out;

    float *p_inps, *p_h0, *p_xproj, *p_gh, *p_outputs, *p_hpart, *p_epart;
    cudaGetSymbolAddress((void**)&p_inps,    g_inps);
    cudaGetSymbolAddress((void**)&p_h0,      g_h0);
    cudaGetSymbolAddress((void**)&p_xproj,   g_xproj);
    cudaGetSymbolAddress((void**)&p_gh,      g_gh);
    cudaGetSymbolAddress((void**)&p_outputs, g_outputs);
    cudaGetSymbolAddress((void**)&p_hpart,   g_hpart);
    cudaGetSymbolAddress((void**)&p_epart,   g_epart);

    zero_acc_kernel<<<1, 32>>>();
    sort_kernel<<<1, B>>>(group_cnt);
    inps_kernel<<<B, 256>>>(enc, segments);

    // h0 = init_state @ W_init^T + b_init     (128 x 512, K=2304)
    gemm_nt_small<<<dim3(H / 64, B / 16), 128>>>(init_state, KIN, W_init, KIN, b_init,
                                                 p_h0, H, KIN);

    // x_proj = inps @ W_ih^T + b_ih           (1536 x 1536, K=1024)
    gemm_nt_128<<<dim3(G3 / 128, (B * S) / 128), 256>>>(p_inps, E2, W_ih, E2, b_ih,
                                                        p_xproj, G3, E2);

    // epart = enc @ W1e^T + b_p1              (16384 x 512, K=1024)  -- the big one
    gemm_nt_128<<<dim3(E / 128, (B * L) / 128), 256>>>(enc, E2, W_p1 + H, H + E2, b_p1,
                                                       p_epart, E, E2);

    // GRU scan: 12 sequential steps
    for (int s = 0; s < S; s++) {
        const float* hprev = s ? (p_outputs + (size_t)(s - 1) * H) : p_h0;
        int lda = s ? (S * H) : H;
        gemm_nt_small<<<dim3(G3 / 64, B / 16), 128>>>(hprev, lda, W_hh, H, b_hh,
                                                      p_gh, G3, H);
        gate_kernel<<<(B * H) / 256, 256>>>(s);
    }

    // hpart = outputs @ W1h^T                 (1536 x 512, K=512)
    gemm_nt_128<<<dim3(E / 128, (B * S) / 128), 256>>>(p_outputs, H, W_p1, H + E2, nullptr,
                                                       p_hpart, E, H);

    stop_loss_kernel<<<B, 128>>>(W_stop, b_stop);
    group_loss_kernel<<<B, 256>>>(segments, W_p2, b_p2);
    finalize_kernel<<<1, 1>>>(out);
}

// round 6
// speedup vs baseline: 2.0303x; 2.0303x over previous
#include <cuda_runtime.h>
#include <cuda_bf16.h>
#include <cstdint>
#include <math.h>

// Problem dims
#define B   128
#define S   12
#define L   128
#define E   512
#define E2  1024
#define H   512
#define G3  1536     // 3*H
#define KIN 2304     // E2 + 2V + P

typedef __nv_bfloat16 bf16;

// ---------------- scratch (device globals, no allocation) ----------------
__device__ __align__(256) int   g_idx[B];
__device__ __align__(256) int   g_gc[B];
__device__ __align__(256) bf16  g_inps_bf[B * S * E2];
__device__ __align__(256) float g_h0[B * H];
__device__ __align__(256) float g_xproj[B * S * G3];
__device__ __align__(256) float g_outputs[B * S * H];
__device__ __align__(256) float g_hpart[B * S * E];
__device__ __align__(256) float g_epart[B * L * E];
__device__ __align__(256) bf16  g_enc_bf[B * L * E2];     // 33.5 MB
__device__ __align__(256) bf16  g_wih_bf[G3 * E2];
__device__ __align__(256) bf16  g_whh_bf[G3 * H];
__device__ __align__(256) bf16  g_winit_bf[H * KIN];
__device__ __align__(256) bf16  g_init_bf[B * KIN];
__device__ __align__(256) bf16  g_w1h_bf[E * H];
__device__ __align__(256) bf16  g_w1e_bf[E * E2];
__device__ __align__(256) bf16  g_h_bf[B * H];            // h0 only (never mutated after)
__device__ __align__(256) bf16  g_out_bf[B * S * H];      // h_s per step
__device__ double g_acc[2];

// ---------------- helpers ----------------
__device__ __forceinline__ float softplusf(float x) {
    return fmaxf(x, 0.f) + log1pf(expf(-fabsf(x)));
}
__device__ __forceinline__ float sigmoidf_(float x) {
    return 1.f / (1.f + expf(-x));
}
__device__ __forceinline__ float tanh_approx(float x) {
    float y;
    asm("tanh.approx.f32 %0, %1;" : "=f"(y) : "f"(x));
    return y;
}
__device__ __forceinline__ uint32_t smem_u32(const void* p) {
    return (uint32_t)__cvta_generic_to_shared(p);
}
__device__ __forceinline__ void cp16(uint32_t dst, const void* src) {
    asm volatile("cp.async.ca.shared.global [%0], [%1], 16;\n" :: "r"(dst), "l"(src));
}
#define CP_COMMIT() asm volatile("cp.async.commit_group;\n" ::: "memory")
#define CP_WAIT1()  asm volatile("cp.async.wait_group 1;\n" ::: "memory")
#define CP_WAIT0()  asm volatile("cp.async.wait_group 0;\n" ::: "memory")

#define MMA_BF16(acc, af, bfrag)                                                   \
    asm volatile("mma.sync.aligned.m16n8k16.row.col.f32.bf16.bf16.f32 "            \
        "{%0,%1,%2,%3}, {%4,%5,%6,%7}, {%8,%9}, {%0,%1,%2,%3};\n"                  \
        : "+f"(acc[0]), "+f"(acc[1]), "+f"(acc[2]), "+f"(acc[3])                   \
        : "r"(af[0]), "r"(af[1]), "r"(af[2]), "r"(af[3]),                          \
          "r"(bfrag[0]), "r"(bfrag[1]))

#define SAS 40   // smem row stride in bf16 elems (80B = 16B-aligned, conflict-free frags)

// ---------------- small utility kernels ----------------
__global__ void zero_acc_kernel() {
    if (threadIdx.x < 2) g_acc[threadIdx.x] = 0.0;
}
__global__ void zero_h0_kernel() {
    int i = blockIdx.x * blockDim.x + threadIdx.x;
    if (i < B * H) g_h0[i] = 0.f;
}
// fp32 -> bf16, contiguous, vectorized by 4
__global__ void conv_bf_kernel(const float* __restrict__ src, bf16* __restrict__ dst, int n) {
    int i = (blockIdx.x * blockDim.x + threadIdx.x) * 4;
    if (i < n) {
        float4 v = *(const float4*)(src + i);
        *(__nv_bfloat162*)(dst + i)     = __floats2bfloat162_rn(v.x, v.y);
        *(__nv_bfloat162*)(dst + i + 2) = __floats2bfloat162_rn(v.z, v.w);
    }
}
// fp32 (row stride ld) -> bf16 packed [rows x cols]
__global__ void conv_bf_strided_kernel(const float* __restrict__ src, int ld,
                                       bf16* __restrict__ dst, int rows, int cols) {
    int q = blockIdx.x * blockDim.x + threadIdx.x;
    int nq = rows * (cols >> 2);
    if (q < nq) {
        int cq = cols >> 2;
        int r = q / cq, c = (q - r * cq) * 4;
        float4 v = *(const float4*)(src + (size_t)r * ld + c);
        bf16* d = dst + (size_t)r * cols + c;
        *(__nv_bfloat162*)(d)     = __floats2bfloat162_rn(v.x, v.y);
        *(__nv_bfloat162*)(d + 2) = __floats2bfloat162_rn(v.z, v.w);
    }
}

// ---------------- stable descending argsort of group_count ----------------
__global__ void sort_kernel(const int* __restrict__ group_count) {
    __shared__ int s_gc[B];
    int i = threadIdx.x;
    int gci = group_count[i];
    s_gc[i] = gci;
    __syncthreads();
    int rank = 0;
    #pragma unroll 8
    for (int j = 0; j < B; j++) {
        int gj = s_gc[j];
        rank += (gj > gci) || (gj == gci && j < i);
    }
    g_idx[rank] = i;
    g_gc[rank]  = gci;
}

// ---------------- inps = alpha @ enc_states -> bf16 ----------------
// alpha from SORTED segments (g_idx); enc stays in ORIGINAL order (matches ref).
__global__ void __launch_bounds__(256) inps_kernel(const float* __restrict__ enc,
                                                   const int* __restrict__ segments) {
    __shared__ float s_a[S][L];
    int b = blockIdx.x, tid = threadIdx.x;
    int src = g_idx[b];

    for (int i = tid; i < S * L; i += 256) {
        int s = i >> 7, l = i & 127;
        int v = (s == 0) ? 0 : segments[(src * S + (s - 1)) * L + l];
        s_a[s][l] = (float)v;
    }
    __syncthreads();
    if (tid < S) {
        float su = 0.f;
        for (int l = 0; l < L; l++) su += s_a[tid][l];
        float inv = 1.f / (su + 1.f);
        for (int l = 0; l < L; l++) s_a[tid][l] *= inv;
    }
    __syncthreads();

    float4 acc[S];
    #pragma unroll
    for (int s = 0; s < S; s++) acc[s] = make_float4(0.f, 0.f, 0.f, 0.f);

    const float* encb = enc + (size_t)b * L * E2;
    int e0 = tid * 4;
    for (int l = 0; l < L; l++) {
        float4 v = *(const float4*)(encb + l * E2 + e0);
        #pragma unroll
        for (int s = 0; s < S; s++) {
            float a = s_a[s][l];
            acc[s].x += a * v.x; acc[s].y += a * v.y;
            acc[s].z += a * v.z; acc[s].w += a * v.w;
        }
    }
    #pragma unroll
    for (int s = 0; s < S; s++) {
        bf16* d = g_inps_bf + ((size_t)(b * S + s)) * E2 + e0;
        *(__nv_bfloat162*)(d)     = __floats2bfloat162_rn(acc[s].x, acc[s].y);
        *(__nv_bfloat162*)(d + 2) = __floats2bfloat162_rn(acc[s].z, acc[s].w);
    }
}

// ---------------- bf16 tensor-core GEMM: C[m,n] = bias[n] + A[m,:]·W[n,:] -----
// Tiles 128x128x32, 256 threads = 8 warps (4m x 2n), warp tile 32x64.
// gridDim.z>1 => split-K with atomicAdd into pre-zeroed C (bias added by z==0).
__global__ void __launch_bounds__(256) mma_gemm(const bf16* __restrict__ A,
                                                const bf16* __restrict__ Wt,
                                                const float* __restrict__ bias,
                                                float* __restrict__ C,
                                                int N, int K, int Kc) {
    __shared__ bf16 sA[2][128 * SAS];
    __shared__ bf16 sB[2][128 * SAS];
    const int tid = threadIdx.x;
    const int bm = blockIdx.y * 128, bn = blockIdx.x * 128;
    const int nkt = Kc / 32;
    const bf16* Ab = A + (size_t)bm * K + blockIdx.z * Kc;
    const bf16* Bb = Wt + (size_t)bn * K + blockIdx.z * Kc;

    const int ar = tid >> 2, as = (tid & 3) * 8;

    cp16(smem_u32(&sA[0][ar * SAS + as]),        Ab + (size_t)ar * K + as);
    cp16(smem_u32(&sA[0][(ar + 64) * SAS + as]), Ab + (size_t)(ar + 64) * K + as);
    cp16(smem_u32(&sB[0][ar * SAS + as]),        Bb + (size_t)ar * K + as);
    cp16(smem_u32(&sB[0][(ar + 64) * SAS + as]), Bb + (size_t)(ar + 64) * K + as);
    CP_COMMIT();

    const int lane = tid & 31, warp = tid >> 5;
    const int wm = warp >> 1, wn = warp & 1;
    const int g = lane >> 2, tq = lane & 3;

    float acc[2][8][4];
    #pragma unroll
    for (int i = 0; i < 2; i++)
        #pragma unroll
        for (int j = 0; j < 8; j++)
            #pragma unroll
            for (int k = 0; k < 4; k++) acc[i][j][k] = 0.f;

    for (int kt = 0; kt < nkt; kt++) {
        int st = kt & 1;
        if (kt + 1 < nkt) {
            int ns = st ^ 1;
            const bf16* An = Ab + (kt + 1) * 32;
            const bf16* Bn = Bb + (kt + 1) * 32;
            cp16(smem_u32(&sA[ns][ar * SAS + as]),        An + (size_t)ar * K + as);
            cp16(smem_u32(&sA[ns][(ar + 64) * SAS + as]), An + (size_t)(ar + 64) * K + as);
            cp16(smem_u32(&sB[ns][ar * SAS + as]),        Bn + (size_t)ar * K + as);
            cp16(smem_u32(&sB[ns][(ar + 64) * SAS + as]), Bn + (size_t)(ar + 64) * K + as);
            CP_COMMIT();
            CP_WAIT1();
        } else {
            CP_WAIT0();
        }
        __syncthreads();
        const bf16* pa = &sA[st][0];
        const bf16* pb = &sB[st][0];
        #pragma unroll
        for (int kk = 0; kk < 32; kk += 16) {
            uint32_t af[2][4], bfr[8][2];
            #pragma unroll
            for (int mf = 0; mf < 2; mf++) {
                int r0 = wm * 32 + mf * 16;
                af[mf][0] = *(const uint32_t*)&pa[(r0 + g) * SAS + kk + 2 * tq];
                af[mf][1] = *(const uint32_t*)&pa[(r0 + g + 8) * SAS + kk + 2 * tq];
                af[mf][2] = *(const uint32_t*)&pa[(r0 + g) * SAS + kk + 2 * tq + 8];
                af[mf][3] = *(const uint32_t*)&pa[(r0 + g + 8) * SAS + kk + 2 * tq + 8];
            }
            #pragma unroll
            for (int nf = 0; nf < 8; nf++) {
                int rn = wn * 64 + nf * 8 + g;
                bfr[nf][0] = *(const uint32_t*)&pb[rn * SAS + kk + 2 * tq];
                bfr[nf][1] = *(const uint32_t*)&pb[rn * SAS + kk + 2 * tq + 8];
            }
            #pragma unroll
            for (int mf = 0; mf < 2; mf++)
                #pragma unroll
                for (int nf = 0; nf < 8; nf++)
                    MMA_BF16(acc[mf][nf], af[mf], bfr[nf]);
        }
        __syncthreads();
    }

    bool single = (gridDim.z == 1);
    #pragma unroll
    for (int mf = 0; mf < 2; mf++) {
        int row0 = bm + wm * 32 + mf * 16 + g;
        #pragma unroll
        for (int nf = 0; nf < 8; nf++) {
            int col = bn + wn * 64 + nf * 8 + 2 * tq;
            float bv0 = 0.f, bv1 = 0.f;
            if (bias != nullptr && blockIdx.z == 0) { bv0 = bias[col]; bv1 = bias[col + 1]; }
            float* c0 = C + (size_t)row0 * N + col;
            float* c1 = C + (size_t)(row0 + 8) * N + col;
            if (single) {
                c0[0] = acc[mf][nf][0] + bv0; c0[1] = acc[mf][nf][1] + bv1;
                c1[0] = acc[mf][nf][2] + bv0; c1[1] = acc[mf][nf][3] + bv1;
            } else {
                atomicAdd(c0,     acc[mf][nf][0] + bv0);
                atomicAdd(c0 + 1, acc[mf][nf][1] + bv1);
                atomicAdd(c1,     acc[mf][nf][2] + bv0);
                atomicAdd(c1 + 1, acc[mf][nf][3] + bv1);
            }
        }
    }
}

// ---------------- fused GRU step: gh-GEMM + gates in one kernel ----------------
// A = h_{s-1}: from g_h_bf (lda=H) for s==0, else g_out_bf at step s-1 (lda=S*H).
// RACE-FREE: g_h_bf / previous g_out_bf slices are only written by PREVIOUS launches.
#define GHS 100   // gh smem stride (floats)
__global__ void __launch_bounds__(256) gru_step(const bf16* __restrict__ Ab, int lda,
                                                const float* __restrict__ b_hh, int s) {
    extern __shared__ char dyn[];
    bf16* sA0 = (bf16*)dyn;                              // [2][128*SAS]
    bf16* sB0 = (bf16*)(dyn + 2 * 128 * SAS * 2);        // [2][96*SAS]
    float* gh = (float*)dyn;                             // overlay [128][GHS]

    const int tid = threadIdx.x;
    const int j0 = blockIdx.x * 32;
    const int nkt = H / 32;

    const int ar = tid >> 2, as = (tid & 3) * 8;
    auto issue = [&](int kt, int stg) {
        int k0 = kt * 32;
        bf16* sa = sA0 + stg * 128 * SAS;
        bf16* sb = sB0 + stg * 96 * SAS;
        cp16(smem_u32(&sa[ar * SAS + as]),        Ab + (size_t)ar * lda + k0 + as);
        cp16(smem_u32(&sa[(ar + 64) * SAS + as]), Ab + (size_t)(ar + 64) * lda + k0 + as);
        int wr0 = ((ar >> 5) * H + j0 + (ar & 31));
        cp16(smem_u32(&sb[ar * SAS + as]), g_whh_bf + (size_t)wr0 * H + k0 + as);
        if (tid < 128) {
            int r2 = ar + 64;   // rows 64..95
            int wr2 = ((r2 >> 5) * H + j0 + (r2 & 31));
            cp16(smem_u32(&sb[r2 * SAS + as]), g_whh_bf + (size_t)wr2 * H + k0 + as);
        }
    };

    issue(0, 0);
    CP_COMMIT();

    const int lane = tid & 31, warp = tid >> 5;
    const int wm = warp >> 1, wn = warp & 1;
    const int g = lane >> 2, tq = lane & 3;

    float acc[2][6][4];
    #pragma unroll
    for (int i = 0; i < 2; i++)
        #pragma unroll
        for (int j = 0; j < 6; j++)
            #pragma unroll
            for (int k = 0; k < 4; k++) acc[i][j][k] = 0.f;

    for (int kt = 0; kt < nkt; kt++) {
        int st = kt & 1;
        if (kt + 1 < nkt) { issue(kt + 1, st ^ 1); CP_COMMIT(); CP_WAIT1(); }
        else              { CP_WAIT0(); }
        __syncthreads();
        const bf16* pa = sA0 + st * 128 * SAS;
        const bf16* pb = sB0 + st * 96 * SAS;
        #pragma unroll
        for (int kk = 0; kk < 32; kk += 16) {
            uint32_t af[2][4], bfr[6][2];
            #pragma unroll
            for (int mf = 0; mf < 2; mf++) {
                int r0 = wm * 32 + mf * 16;
                af[mf][0] = *(const uint32_t*)&pa[(r0 + g) * SAS + kk + 2 * tq];
                af[mf][1] = *(const uint32_t*)&pa[(r0 + g + 8) * SAS + kk + 2 * tq];
                af[mf][2] = *(const uint32_t*)&pa[(r0 + g) * SAS + kk + 2 * tq + 8];
                af[mf][3] = *(const uint32_t*)&pa[(r0 + g + 8) * SAS + kk + 2 * tq + 8];
            }
            #pragma unroll
            for (int nf = 0; nf < 6; nf++) {
                int rn = wn * 48 + nf * 8 + g;
                bfr[nf][0] = *(const uint32_t*)&pb[rn * SAS + kk + 2 * tq];
                bfr[nf][1] = *(const uint32_t*)&pb[rn * SAS + kk + 2 * tq + 8];
            }
            #pragma unroll
            for (int mf = 0; mf < 2; mf++)
                #pragma unroll
                for (int nf = 0; nf < 6; nf++)
                    MMA_BF16(acc[mf][nf], af[mf], bfr[nf]);
        }
        __syncthreads();
    }

    // stage gh (with b_hh bias) through smem  (cols: [0,32)=r, [32,64)=z, [64,96)=n)
    #pragma unroll
    for (int mf = 0; mf < 2; mf++) {
        int row0 = wm * 32 + mf * 16 + g;
        #pragma unroll
        for (int nf = 0; nf < 6; nf++) {
            int col = wn * 48 + nf * 8 + 2 * tq;
            int gate = col >> 5, jj = col & 31;
            float bv0 = b_hh[gate * H + j0 + jj];
            float bv1 = b_hh[gate * H + j0 + jj + 1];
            gh[row0 * GHS + col]           = acc[mf][nf][0] + bv0;
            gh[row0 * GHS + col + 1]       = acc[mf][nf][1] + bv1;
            gh[(row0 + 8) * GHS + col]     = acc[mf][nf][2] + bv0;
            gh[(row0 + 8) * GHS + col + 1] = acc[mf][nf][3] + bv1;
        }
    }
    __syncthreads();

    // gates: thread -> (j = lane, 16 batches)
    int jl = tid & 31;
    int j  = j0 + jl;
    int b0 = (tid >> 5) * 16;
    for (int i = 0; i < 16; i++) {
        int b = b0 + i;
        float hr = gh[b * GHS + jl];
        float hz = gh[b * GHS + 32 + jl];
        float hn = gh[b * GHS + 64 + jl];
        const float* xp = g_xproj + ((size_t)b * S + s) * G3 + j;
        float ir = xp[0], iz = xp[H], inn = xp[2 * H];
        float r = sigmoidf_(ir + hr);
        float z = sigmoidf_(iz + hz);
        float n = tanhf(inn + r * hn);
        float hp = s ? g_outputs[((size_t)b * S + s - 1) * H + j]
                     : g_h0[(size_t)b * H + j];
        float hnew = (1.f - z) * n + z * hp;
        g_outputs[((size_t)b * S + s) * H + j] = hnew;
        g_out_bf[((size_t)b * S + s) * H + j] = __float2bfloat16_rn(hnew);
    }
}

// ---------------- stop loss ----------------
__global__ void __launch_bounds__(128) stop_loss_kernel(const float* __restrict__ W_stop,
                                                        const float* __restrict__ b_stop) {
    __shared__ float s_w[H];
    int b = blockIdx.x, tid = threadIdx.x;
    int gcb = g_gc[b];
    for (int i = tid; i < H; i += 128) s_w[i] = W_stop[i];
    __syncthreads();
    int w = tid >> 5, lane = tid & 31;
    float acc = 0.f;
    float bs = __ldg(b_stop);
    for (int s = w; s < gcb; s += 4) {
        const float* h = g_outputs + (size_t)(b * S + s) * H;
        float p = 0.f;
        for (int j = lane; j < H; j += 32) p += h[j] * s_w[j];
        #pragma unroll
        for (int off = 16; off; off >>= 1) p += __shfl_down_sync(0xffffffffu, p, off);
        if (lane == 0) {
            float logit = p + bs;
            float lab = (s == gcb - 1) ? 1.f : 0.f;
            acc += softplusf(logit) - logit * lab;
        }
    }
    if (lane == 0) atomicAdd(&g_acc[0], (double)acc);
}

// ---------------- group (plan) loss ----------------
__global__ void __launch_bounds__(256) group_loss_kernel(const int* __restrict__ segments,
                                                         const float* __restrict__ W_p2,
                                                         const float* __restrict__ b_p2) {
    __shared__ float s_h[S * E];
    __shared__ float s_w2[E];
    __shared__ float s_ep[E];
    __shared__ float s_tg[S * L];
    int b = blockIdx.x, tid = threadIdx.x;
    int src = g_idx[b], gcb = g_gc[b];

    for (int i = tid; i < E; i += 256) s_w2[i] = W_p2[i];
    for (int i = tid; i < S * E; i += 256) s_h[i] = g_hpart[(size_t)b * S * E + i];
    for (int i = tid; i < S * L; i += 256) s_tg[i] = (float)segments[(size_t)src * S * L + i];
    __syncthreads();

    int w = tid >> 5, lane = tid & 31;
    float bp2 = __ldg(b_p2);
    float accw = 0.f;

    for (int l = 0; l < L; l++) {
        const float* ep = g_epart + (size_t)(b * L + l) * E;
        s_ep[tid]       = ep[tid];
        s_ep[tid + 256] = ep[tid + 256];
        __syncthreads();
        for (int s = w; s < gcb; s += 8) {
            const float* hs = &s_h[s * E];
            float p = 0.f;
            #pragma unroll 4
            for (int e = lane; e < E; e += 32)
                p += tanh_approx(hs[e] + s_ep[e]) * s_w2[e];
            #pragma unroll
            for (int off = 16; off; off >>= 1) p += __shfl_down_sync(0xffffffffu, p, off);
            if (lane == 0) {
                float logit = p + bp2;
                float t = s_tg[s * L + l];
                accw += softplusf(logit) - logit * t;
            }
        }
        __syncthreads();
    }
    if (lane == 0) atomicAdd(&g_acc[1], (double)accw);
}

// ---------------- finalize ----------------
__global__ void finalize_kernel(float* out) {
    double ms = 0.0;
    for (int b = 0; b < B; b++) ms += (double)g_gc[b];
    out[0] = (float)(g_acc[0] / ms);
    out[1] = (float)(g_acc[1] / (ms * (double)L));
}

// ---------------- launch ----------------
extern "C" void kernel_launch(void* const* d_in, const int* in_sizes, int n_in,
                              void* d_out, int out_size) {
    (void)in_sizes; (void)n_in; (void)out_size;
    const float* enc        = (const float*)d_in[0];
    const int*   segments   = (const int*)d_in[1];
    const int*   group_cnt  = (const int*)d_in[2];
    const float* init_state = (const float*)d_in[3];
    const float* W_init     = (const float*)d_in[4];
    const float* b_init     = (const float*)d_in[5];
    const float* W_ih       = (const float*)d_in[6];
    const float* b_ih       = (const float*)d_in[7];
    const float* W_hh       = (const float*)d_in[8];
    const float* b_hh       = (const float*)d_in[9];
    const float* W_p1       = (const float*)d_in[10];
    const float* b_p1       = (const float*)d_in[11];
    const float* W_p2       = (const float*)d_in[12];
    const float* b_p2       = (const float*)d_in[13];
    const float* W_stop     = (const float*)d_in[14];
    const float* b_stop     = (const float*)d_in[15];
    float* out = (float*)d_out;

    // Idempotent attribute set each call (no static guards allowed).
    cudaFuncSetAttribute(gru_step, cudaFuncAttributeMaxDynamicSharedMemorySize, 51200);

    float *p_h0, *p_xproj, *p_outputs, *p_hpart, *p_epart;
    bf16 *p_enc_bf, *p_wih_bf, *p_whh_bf, *p_winit_bf, *p_init_bf, *p_w1h_bf, *p_w1e_bf;
    bf16 *p_inps_bf, *p_h_bf, *p_out_bf;
    cudaGetSymbolAddress((void**)&p_h0,       g_h0);
    cudaGetSymbolAddress((void**)&p_xproj,    g_xproj);
    cudaGetSymbolAddress((void**)&p_outputs,  g_outputs);
    cudaGetSymbolAddress((void**)&p_hpart,    g_hpart);
    cudaGetSymbolAddress((void**)&p_epart,    g_epart);
    cudaGetSymbolAddress((void**)&p_enc_bf,   g_enc_bf);
    cudaGetSymbolAddress((void**)&p_wih_bf,   g_wih_bf);
    cudaGetSymbolAddress((void**)&p_whh_bf,   g_whh_bf);
    cudaGetSymbolAddress((void**)&p_winit_bf, g_winit_bf);
    cudaGetSymbolAddress((void**)&p_init_bf,  g_init_bf);
    cudaGetSymbolAddress((void**)&p_w1h_bf,   g_w1h_bf);
    cudaGetSymbolAddress((void**)&p_w1e_bf,   g_w1e_bf);
    cudaGetSymbolAddress((void**)&p_inps_bf,  g_inps_bf);
    cudaGetSymbolAddress((void**)&p_h_bf,     g_h_bf);
    cudaGetSymbolAddress((void**)&p_out_bf,   g_out_bf);

    zero_acc_kernel<<<1, 32>>>();
    sort_kernel<<<1, B>>>(group_cnt);

    // fp32 -> bf16 conversions
    conv_bf_kernel<<<(B * L * E2 / 4 + 255) / 256, 256>>>(enc, p_enc_bf, B * L * E2);
    conv_bf_kernel<<<(G3 * E2 / 4 + 255) / 256, 256>>>(W_ih, p_wih_bf, G3 * E2);
    conv_bf_kernel<<<(G3 * H / 4 + 255) / 256, 256>>>(W_hh, p_whh_bf, G3 * H);
    conv_bf_kernel<<<(H * KIN / 4 + 255) / 256, 256>>>(W_init, p_winit_bf, H * KIN);
    conv_bf_kernel<<<(B * KIN / 4 + 255) / 256, 256>>>(init_state, p_init_bf, B * KIN);
    conv_bf_strided_kernel<<<(E * H / 4 + 255) / 256, 256>>>(W_p1, H + E2, p_w1h_bf, E, H);
    conv_bf_strided_kernel<<<(E * E2 / 4 + 255) / 256, 256>>>(W_p1 + H, H + E2, p_w1e_bf, E, E2);

    inps_kernel<<<B, 256>>>(enc, segments);

    // h0 = init_state @ W_init^T + b_init  (split-K: 4n x 1m x 6kz = 24 blocks)
    zero_h0_kernel<<<(B * H + 255) / 256, 256>>>();
    mma_gemm<<<dim3(H / 128, 1, 6), 256>>>(p_init_bf, p_winit_bf, b_init, p_h0,
                                           H, KIN, KIN / 6);
    conv_bf_kernel<<<(B * H / 4 + 255) / 256, 256>>>(p_h0, p_h_bf, B * H);

    // x_proj = inps @ W_ih^T + b_ih   (1536 x 1536, K=1024)
    mma_gemm<<<dim3(G3 / 128, (B * S) / 128, 1), 256>>>(p_inps_bf, p_wih_bf, b_ih,
                                                        p_xproj, G3, E2, E2);
    // epart = enc @ W1e^T + b_p1      (16384 x 512, K=1024)
    mma_gemm<<<dim3(E / 128, (B * L) / 128, 1), 256>>>(p_enc_bf, p_w1e_bf, b_p1,
                                                       p_epart, E, E2, E2);

    // GRU scan: 12 fused steps (A = h_{s-1}, read-only source per step => no race)
    for (int s = 0; s < S; s++) {
        const bf16* Ab = s ? (p_out_bf + (size_t)(s - 1) * H) : p_h_bf;
        int lda = s ? (S * H) : H;
        gru_step<<<16, 256, 51200>>>(Ab, lda, b_hh, s);
    }

    // hpart = outputs @ W1h^T         (1536 x 512, K=512)
    mma_gemm<<<dim3(E / 128, (B * S) / 128, 1), 256>>>(p_out_bf, p_w1h_bf, nullptr,
                                                       p_hpart, E, H, H);

    stop_loss_kernel<<<B, 128>>>(W_stop, b_stop);
    group_loss_kernel<<<B, 256>>>(segments, W_p2, b_p2);
    finalize_kernel<<<1, 1>>>(out);
}